// round 13
// baseline (speedup 1.0000x reference)
#include <cuda_runtime.h>
#include <cuda_bf16.h>

// SurvEMD fused forward.
// R12->R13: thread-per-row rewrite. Cooperative coalesced staging of 128 rows
// into xor-swizzled smem (double-buffered), then each thread computes its row
// serially with the moment decomposition
//   loss = inv^2 * Sum(p^2) - 2*inv*Sum(p*T) + Sum(T^2),  p = unnorm. prefix
// which needs ONE streaming pass and no shuffles. ~24 warp-instr/row vs 45.

#define NBINS       64
#define BLOCK_T     128
#define GRID_B      2048
#define ROWS_PER_IT (GRID_B * BLOCK_T)          // 262144
#define STAGE_F4    (BLOCK_T * 16)              // 2048 float4 per buffer
#define SMEM_BYTES  (2 * STAGE_F4 * 16)         // 65536
#define EXP_NEG20   2.0611536e-09f              // expf(-20.0f)
#define FULL        0xFFFFFFFFu

__device__ float    g_partials[GRID_B];
__device__ unsigned g_count;                    // zero-init; reset by last block

__device__ __forceinline__ float frcp(float x) {
    float r;
    asm("rcp.approx.f32 %0, %1;" : "=f"(r) : "f"(x));
    return r;
}

// Cooperative coalesced load of 128 rows (2048 float4) into a swizzled buffer.
// buf[row*16 + (col ^ (row&15))] = y4[srcRow*16 + col]  -> conflict-free STS/LDS.
__device__ __forceinline__ void load_stage(float4* __restrict__ buf,
                                           const float4* __restrict__ y4,
                                           int rows0, int tid, int B)
{
    #pragma unroll
    for (int k = 0; k < 16; k++) {
        const int lin  = k * BLOCK_T + tid;
        const int rowL = lin >> 4;
        const int col  = lin & 15;
        const int srcRow = min(rows0 + rowL, B - 1);
        buf[rowL * 16 + (col ^ (rowL & 15))] = y4[(size_t)srcRow * 16 + col];
    }
}

__global__ __launch_bounds__(BLOCK_T, 3)
void survemd_main(const float* __restrict__ y_hat,
                  const int* __restrict__ t_in,
                  const int* __restrict__ e_in,
                  float* __restrict__ out,
                  int B)
{
    extern __shared__ float4 stage[];           // [2][2048]
    const int tid  = threadIdx.x;
    const int lane = tid & 31;
    const int wid  = tid >> 5;
    const float4* y4 = (const float4*)y_hat;

    const int blockRow = blockIdx.x * BLOCK_T;
    const int nIter = (B + ROWS_PER_IT - 1) / ROWS_PER_IT;   // 4 for bench shape

    float acc = 0.0f;

    // preload iteration 0 into buffer 0
    load_stage(stage, y4, blockRow, tid, B);

    for (int it = 0; it < nIter; it++) {
        const int rows0 = it * ROWS_PER_IT + blockRow;
        __syncthreads();                         // current stage visible

        // issue next iteration's loads before compute (overlap DRAM w/ math)
        if (it + 1 < nIter)
            load_stage(stage + ((it + 1) & 1) * STAGE_F4, y4,
                       rows0 + ROWS_PER_IT, tid, B);

        // ---- per-thread row compute ----
        const int r  = rows0 + tid;
        const int rc = min(r, B - 1);
        const int tr = t_in[rc];
        const int er = e_in[rc];

        const bool  cen = (er == 0);
        const float tf  = (float)tr;
        const float kf  = cen ? (64.0f - tf) : 1.0f;
        const float q1  = frcp(fmaf(64.0f - kf, EXP_NEG20, kf));
        const float q0  = EXP_NEG20 * q1;
        const float dq  = q1 - q0;
        const float thr = cen ? tf : 3.0e38f;
        const float isc = cen ? 0.015625f : 1.0f;
        const float nb  = -tf * isc;
        const float dqe = cen ? (dq * 64.0f) : dq;

        float p = 0.0f, A = 0.0f, Bx = 0.0f, Cx = 0.0f;

        const float4* st = stage + (it & 1) * STAGE_F4 + tid * 16;
        const int sw = tid & 15;

        #define ELEM(yv, J) {                                        \
            const float jf  = (float)(J);                            \
            const float jp1 = jf + 1.0f;                             \
            const float l   = (jf >= thr) ? 10.0f : (yv);            \
            p += __expf(l);                                          \
            const float c1 = __saturatef(fmaf(jp1, isc, nb));        \
            const float T  = fmaf(c1, dqe, jp1 * q0);                \
            A  = fmaf(p, p, A);                                      \
            Bx = fmaf(p, T, Bx);                                     \
            Cx = fmaf(T, T, Cx);                                     \
        }

        #pragma unroll
        for (int c = 0; c < 16; c++) {
            const float4 v = st[c ^ sw];
            ELEM(v.x, 4 * c + 0)
            ELEM(v.y, 4 * c + 1)
            ELEM(v.z, 4 * c + 2)
            ELEM(v.w, 4 * c + 3)
        }
        #undef ELEM

        const float inv  = frcp(p);              // p == row total
        const float loss = fmaf(inv, fmaf(inv, A, -(Bx + Bx)), Cx);
        if (r < B) acc += loss;
    }

    // ---- block reduction ----
    #pragma unroll
    for (int off = 16; off > 0; off >>= 1)
        acc += __shfl_xor_sync(FULL, acc, off);

    __shared__ float warpSums[BLOCK_T / 32];
    if (lane == 0) warpSums[wid] = acc;
    __syncthreads();

    __shared__ bool isLast;
    if (tid == 0) {
        float sm = 0.0f;
        #pragma unroll
        for (int i = 0; i < BLOCK_T / 32; i++) sm += warpSums[i];
        g_partials[blockIdx.x] = sm;
        __threadfence();
        unsigned ticket = atomicAdd(&g_count, 1u);
        isLast = (ticket == (unsigned)(gridDim.x - 1));
    }
    __syncthreads();

    if (isLast) {
        float sm = 0.0f;
        for (int i = tid; i < GRID_B; i += BLOCK_T)
            sm += ((volatile float*)g_partials)[i];

        #pragma unroll
        for (int off = 16; off > 0; off >>= 1)
            sm += __shfl_xor_sync(FULL, sm, off);

        __shared__ float finalSums[BLOCK_T / 32];
        if (lane == 0) finalSums[wid] = sm;
        __syncthreads();

        if (tid == 0) {
            float tot = 0.0f;
            #pragma unroll
            for (int i = 0; i < BLOCK_T / 32; i++) tot += finalSums[i];
            out[0] = tot / (float)B;
            g_count = 0;                        // reset for next graph replay
        }
    }
}

extern "C" void kernel_launch(void* const* d_in, const int* in_sizes, int n_in,
                              void* d_out, int out_size)
{
    const float* y_hat = (const float*)d_in[0];
    const int*   t     = (const int*)d_in[1];
    const int*   e     = (const int*)d_in[2];
    float*       out   = (float*)d_out;
    const int B = in_sizes[1];   // element count of t

    cudaFuncSetAttribute(survemd_main,
                         cudaFuncAttributeMaxDynamicSharedMemorySize, SMEM_BYTES);
    survemd_main<<<GRID_B, BLOCK_T, SMEM_BYTES>>>(y_hat, t, e, out, B);
}

// round 14
// speedup vs baseline: 1.1856x; 1.1856x over previous
#include <cuda_runtime.h>
#include <cuda_bf16.h>

// SurvEMD fused forward (math: see prior rounds). Base = R9 (best, 56.1us).
// R13->R14, three surgical changes:
//  1. counted main loop + pointer increments, launch_bounds(256,5) (<=51 regs)
//  2. predicated chunk-load skip: censored rows don't fetch y for chunks fully
//     in the replaced tail (cen && t <= 16c) -> ~19% less DRAM traffic
//  3. tot-space loss: m = p_unnorm - tot*T, loss = sum(m^2)*inv^2; rcp moves
//     off the critical path, E*inv multiply per chunk removed.

#define NBINS       64
#define BLOCK_T     256
#define GRID_B      2048
#define EXP_NEG20   2.0611536e-09f   // expf(-20.0f)
#define FULL        0xFFFFFFFFu

__device__ float    g_partials[GRID_B];
__device__ unsigned g_count;         // zero-init; reset by last block each launch

__device__ __forceinline__ float frcp(float x) {
    float r;
    asm("rcp.approx.f32 %0, %1;" : "=f"(r) : "f"(x));
    return r;
}

// One 64-bin row over 4 lanes; lane owns f4 chunks 4c+s (elements 16c+4s+i).
// Loads are done by the caller (so it can predicate them); this computes loss.
__device__ __forceinline__ float row_body(int tr, int er,
                                          const float4* ya,
                                          float b0f, float b1f, float b2f, float b3f,
                                          int s)
{
    const bool  cen = (er == 0);
    const float tf  = (float)tr;
    const float kf  = cen ? (64.0f - tf) : 1.0f;
    const float q1  = frcp(fmaf(64.0f - kf, EXP_NEG20, kf));
    const float q0  = EXP_NEG20 * q1;
    const float dq  = q1 - q0;
    const float thr = cen ? tf : 3.0e38f;
    const float isc = cen ? 0.015625f : 1.0f;
    const float nb  = -tf * isc;
    const float ndqe = cen ? (dq * -64.0f) : -dq;

    // exps + in-lane inclusive partials per 4-element chunk
    float sl[4][4];
    #pragma unroll
    for (int c = 0; c < 4; c++) {
        const float thrc = thr - 16.0f * (float)c;
        float e0 = __expf((b0f > thrc) ? 10.0f : ya[c].x);
        float e1 = __expf((b1f > thrc) ? 10.0f : ya[c].y);
        float e2 = __expf((b2f > thrc) ? 10.0f : ya[c].z);
        float e3 = __expf((b3f > thrc) ? 10.0f : ya[c].w);
        sl[c][0] = e0;
        sl[c][1] = sl[c][0] + e1;
        sl[c][2] = sl[c][1] + e2;
        sl[c][3] = sl[c][2] + e3;
    }

    // exclusive quad prefixes (unnormalized): width-4 shfl scan + carry chain
    float E[4];
    float carry = 0.0f;
    #pragma unroll
    for (int c = 0; c < 4; c++) {
        float incl = sl[c][3];
        float v = __shfl_up_sync(FULL, incl, 1, 4);
        if (s >= 1) incl += v;
        v = __shfl_up_sync(FULL, incl, 2, 4);
        if (s >= 2) incl += v;
        const float W = __shfl_sync(FULL, incl, 3, 4);   // chunk total
        E[c] = carry + (incl - sl[c][3]);
        carry += W;
    }

    const float tot  = carry;            // row softmax denominator (unnorm)
    const float inv  = frcp(tot);        // off critical path of loss loop
    const float nq0t = -q0 * tot;
    const float ndqet = ndqe * tot;

    // loss in tot-space: m = (E + s) - tot*T ; r = sum m^2 ; loss = r*inv^2
    float r = 0.0f;
    #pragma unroll
    for (int c = 0; c < 4; c++) {
        const float hq = fmaf(16.0f * (float)c, nq0t, E[c]);
        const float hb = fmaf(16.0f * (float)c, isc, nb);

        float c0 = __saturatef(fmaf(b0f, isc, hb));
        float c1 = __saturatef(fmaf(b1f, isc, hb));
        float c2 = __saturatef(fmaf(b2f, isc, hb));
        float c3 = __saturatef(fmaf(b3f, isc, hb));

        float w0 = fmaf(c0, ndqet, fmaf(b0f, nq0t, hq));
        float w1 = fmaf(c1, ndqet, fmaf(b1f, nq0t, hq));
        float w2 = fmaf(c2, ndqet, fmaf(b2f, nq0t, hq));
        float w3 = fmaf(c3, ndqet, fmaf(b3f, nq0t, hq));

        float m0 = sl[c][0] + w0;
        float m1 = sl[c][1] + w1;
        float m2 = sl[c][2] + w2;
        float m3 = sl[c][3] + w3;

        r = fmaf(m0, m0, r);
        r = fmaf(m1, m1, r);
        r = fmaf(m2, m2, r);
        r = fmaf(m3, m3, r);
    }
    return r * (inv * inv);
}

__global__ __launch_bounds__(BLOCK_T, 5)
void survemd_main(const float* __restrict__ y_hat,
                  const int* __restrict__ t_in,
                  const int* __restrict__ e_in,
                  float* __restrict__ out,
                  int B)
{
    const int lane = threadIdx.x & 31;
    const int s    = lane & 3;    // sub-lane within row (owns f4 indices 4c+s)
    const int g    = lane >> 2;   // row within the warp's 8-row group
    const int wid  = threadIdx.x >> 5;

    const int warpsPerBlock = BLOCK_T / 32;
    const int gwarp   = blockIdx.x * warpsPerBlock + wid;
    const int wstride = GRID_B * warpsPerBlock * 8;     // rows per grid-stride step
    const int myrow   = gwarp * 8 + g;                  // < wstride always

    // per-lane element base: jp1(c,i) = (4s + i + 1) + 16c
    const float b0f = (float)(4 * s + 1);
    const float b1f = b0f + 1.0f;
    const float b2f = b0f + 2.0f;
    const float b3f = b0f + 3.0f;

    const int nIter   = B / wstride;        // 8 for the bench shape
    const int remBase = nIter * wstride;    // == B for the bench shape

    const int*    tp = t_in + myrow;
    const int*    ep = e_in + myrow;
    const float4* yp = (const float4*)y_hat + (size_t)myrow * 16 + s;

    float acc = 0.0f;

    #pragma unroll 1
    for (int k = 0; k < nIter; k++) {
        const int tr = *tp;
        const int er = *ep;
        const bool live = (er != 0);   // uncensored: always load

        // predicated chunk loads: skip chunk c when censored && t <= 16c
        // (every element of that chunk is replaced by logit 10; y unused).
        float4 ya[4];
        if (live || tr >  0) ya[0] = yp[0];
        if (live || tr > 16) ya[1] = yp[4];
        if (live || tr > 32) ya[2] = yp[8];
        if (live || tr > 48) ya[3] = yp[12];

        acc += row_body(tr, er, ya, b0f, b1f, b2f, b3f, s);

        tp += wstride;
        ep += wstride;
        yp += (size_t)wstride * 16;
    }

    // generic masked tail (never taken when B % wstride == 0)
    if (remBase < B) {
        const int row  = remBase + myrow;
        const int rowc = min(row, B - 1);
        const float vm = (row < B) ? 1.0f : 0.0f;
        const int tr = t_in[rowc];
        const int er = e_in[rowc];
        const float4* zp = (const float4*)y_hat + (size_t)rowc * 16 + s;
        float4 ya[4] = {zp[0], zp[4], zp[8], zp[12]};
        acc = fmaf(vm, row_body(tr, er, ya, b0f, b1f, b2f, b3f, s), acc);
    }

    // block reduction (warp sum covers all 8 rows' lane partials)
    #pragma unroll
    for (int off = 16; off > 0; off >>= 1)
        acc += __shfl_xor_sync(FULL, acc, off);

    __shared__ float warpSums[BLOCK_T / 32];
    if (lane == 0) warpSums[wid] = acc;
    __syncthreads();

    __shared__ bool isLast;
    if (threadIdx.x == 0) {
        float sm = 0.0f;
        #pragma unroll
        for (int i = 0; i < BLOCK_T / 32; i++) sm += warpSums[i];
        g_partials[blockIdx.x] = sm;
        __threadfence();
        unsigned ticket = atomicAdd(&g_count, 1u);
        isLast = (ticket == (unsigned)(gridDim.x - 1));
    }
    __syncthreads();

    // last block reduces all partials (deterministic order) and resets counter
    if (isLast) {
        float sm = 0.0f;
        for (int i = threadIdx.x; i < GRID_B; i += BLOCK_T)
            sm += ((volatile float*)g_partials)[i];

        #pragma unroll
        for (int off = 16; off > 0; off >>= 1)
            sm += __shfl_xor_sync(FULL, sm, off);

        __shared__ float finalSums[BLOCK_T / 32];
        if (lane == 0) finalSums[wid] = sm;
        __syncthreads();

        if (threadIdx.x == 0) {
            float tot = 0.0f;
            #pragma unroll
            for (int i = 0; i < BLOCK_T / 32; i++) tot += finalSums[i];
            out[0] = tot / (float)B;
            g_count = 0;   // reset for next graph replay
        }
    }
}

extern "C" void kernel_launch(void* const* d_in, const int* in_sizes, int n_in,
                              void* d_out, int out_size)
{
    const float* y_hat = (const float*)d_in[0];
    const int*   t     = (const int*)d_in[1];
    const int*   e     = (const int*)d_in[2];
    float*       out   = (float*)d_out;
    const int B = in_sizes[1];   // element count of t

    survemd_main<<<GRID_B, BLOCK_T>>>(y_hat, t, e, out, B);
}

// round 15
// speedup vs baseline: 1.4149x; 1.1934x over previous
#include <cuda_runtime.h>
#include <cuda_bf16.h>

// SurvEMD fused forward (math: see prior rounds). Base = R9 (best, 56.1us),
// load path and loop structure UNTOUCHED (R14's load-gating regressed).
// R14->R15, issue-slot cuts only:
//  1. tot-space loss: m = p_unnorm - tot*T, loss = sum(m^2)*inv^2
//     (rel_err 0.0 verified in R14; removes E*inv, rcp off critical path)
//  2. f32x2 packed loss chain (fma.rn.f32x2 / add.rn.f32x2): 16 scalar
//     FMA/ADD -> 8 packed + 5 packs per chunk.

#define NBINS       64
#define BLOCK_T     256
#define GRID_B      2048
#define EXP_NEG20   2.0611536e-09f   // expf(-20.0f)
#define FULL        0xFFFFFFFFu

__device__ float    g_partials[GRID_B];
__device__ unsigned g_count;         // zero-init; reset by last block each launch

__device__ __forceinline__ float frcp(float x) {
    float r;
    asm("rcp.approx.f32 %0, %1;" : "=f"(r) : "f"(x));
    return r;
}

__device__ __forceinline__ unsigned long long pk2(float lo, float hi) {
    unsigned long long r;
    asm("mov.b64 %0, {%1, %2};" : "=l"(r) : "f"(lo), "f"(hi));
    return r;
}
__device__ __forceinline__ unsigned long long fma2(unsigned long long a,
                                                   unsigned long long b,
                                                   unsigned long long c) {
    unsigned long long d;
    asm("fma.rn.f32x2 %0, %1, %2, %3;" : "=l"(d) : "l"(a), "l"(b), "l"(c));
    return d;
}
__device__ __forceinline__ unsigned long long add2(unsigned long long a,
                                                   unsigned long long b) {
    unsigned long long d;
    asm("add.rn.f32x2 %0, %1, %2;" : "=l"(d) : "l"(a), "l"(b));
    return d;
}
__device__ __forceinline__ void upk2(unsigned long long v, float& lo, float& hi) {
    asm("mov.b64 {%0, %1}, %2;" : "=f"(lo), "=f"(hi) : "l"(v));
}

__global__ __launch_bounds__(BLOCK_T, 5)
void survemd_main(const float* __restrict__ y_hat,
                  const int* __restrict__ t_in,
                  const int* __restrict__ e_in,
                  float* __restrict__ out,
                  int B)
{
    const int lane = threadIdx.x & 31;
    const int s    = lane & 3;    // sub-lane within row (owns f4 indices 4c+s)
    const int g    = lane >> 2;   // row within the warp's 8-row group
    const int wid  = threadIdx.x >> 5;

    const int warpsPerBlock = BLOCK_T / 32;
    const int gwarp   = blockIdx.x * warpsPerBlock + wid;
    const int wstride = GRID_B * warpsPerBlock * 8;     // rows per grid-stride step

    // per-lane element base: jp1(c,i) = (4s + i + 1) + 16c
    const float b0f = (float)(4 * s + 1);
    const float b1f = b0f + 1.0f;
    const float b2f = b0f + 2.0f;
    const float b3f = b0f + 3.0f;
    const unsigned long long b01 = pk2(b0f, b1f);
    const unsigned long long b23 = pk2(b2f, b3f);

    float acc = 0.0f;

    for (int base = gwarp * 8; base < B; base += wstride) {
        const int   row   = base + g;
        const int   rowc  = min(row, B - 1);
        const float vmask = (row < B) ? 1.0f : 0.0f;

        const int tr = t_in[rowc];
        const int er = e_in[rowc];

        // interleaved float4 loads: f4 index = rowc*16 + 4c + s
        const float4* yrow = (const float4*)y_hat + (size_t)rowc * 16 + s;
        float4 ya[4];
        ya[0] = yrow[0];
        ya[1] = yrow[4];
        ya[2] = yrow[8];
        ya[3] = yrow[12];

        // row params
        const bool  cen = (er == 0);
        const float tf  = (float)tr;
        const float kf  = cen ? (64.0f - tf) : 1.0f;
        const float q1  = frcp(fmaf(64.0f - kf, EXP_NEG20, kf));
        const float q0  = EXP_NEG20 * q1;
        const float dq  = q1 - q0;
        const float thr = cen ? tf : 3.0e38f;
        const float isc = cen ? 0.015625f : 1.0f;
        const float nb  = -tf * isc;
        const float ndqe = cen ? (dq * -64.0f) : -dq;

        // exps + in-lane inclusive partials per 4-element chunk
        float sl[4][4];
        #pragma unroll
        for (int c = 0; c < 4; c++) {
            const float thrc = thr - 16.0f * (float)c;
            float e0 = __expf((b0f > thrc) ? 10.0f : ya[c].x);
            float e1 = __expf((b1f > thrc) ? 10.0f : ya[c].y);
            float e2 = __expf((b2f > thrc) ? 10.0f : ya[c].z);
            float e3 = __expf((b3f > thrc) ? 10.0f : ya[c].w);
            sl[c][0] = e0;
            sl[c][1] = sl[c][0] + e1;
            sl[c][2] = sl[c][1] + e2;
            sl[c][3] = sl[c][2] + e3;
        }

        // exclusive quad prefixes (unnormalized): width-4 shfl scan + carry
        float E[4];
        float carry = 0.0f;
        #pragma unroll
        for (int c = 0; c < 4; c++) {
            float incl = sl[c][3];
            float v = __shfl_up_sync(FULL, incl, 1, 4);
            if (s >= 1) incl += v;
            v = __shfl_up_sync(FULL, incl, 2, 4);
            if (s >= 2) incl += v;
            const float W = __shfl_sync(FULL, incl, 3, 4);   // chunk total
            E[c] = carry + (incl - sl[c][3]);
            carry += W;
        }

        const float tot   = carry;          // row softmax denominator (unnorm)
        const float inv   = frcp(tot);      // off critical path
        const float nq0t  = -q0 * tot;
        const float ndqet = ndqe * tot;
        const unsigned long long nq0t2  = pk2(nq0t, nq0t);
        const unsigned long long ndqet2 = pk2(ndqet, ndqet);

        // loss in tot-space, f32x2 packed:
        // m = (E + s) - tot*T ; r = sum m^2 ; loss = r * inv^2
        unsigned long long racc01 = 0ull, racc23 = 0ull;
        #pragma unroll
        for (int c = 0; c < 4; c++) {
            const float hq = fmaf(16.0f * (float)c, nq0t, E[c]);
            const float hb = fmaf(16.0f * (float)c, isc, nb);

            const float c0 = __saturatef(fmaf(b0f, isc, hb));
            const float c1 = __saturatef(fmaf(b1f, isc, hb));
            const float c2 = __saturatef(fmaf(b2f, isc, hb));
            const float c3 = __saturatef(fmaf(b3f, isc, hb));

            const unsigned long long hq2 = pk2(hq, hq);
            const unsigned long long u01 = fma2(b01, nq0t2, hq2);
            const unsigned long long u23 = fma2(b23, nq0t2, hq2);
            const unsigned long long w01 = fma2(pk2(c0, c1), ndqet2, u01);
            const unsigned long long w23 = fma2(pk2(c2, c3), ndqet2, u23);
            const unsigned long long m01 = add2(pk2(sl[c][0], sl[c][1]), w01);
            const unsigned long long m23 = add2(pk2(sl[c][2], sl[c][3]), w23);
            racc01 = fma2(m01, m01, racc01);
            racc23 = fma2(m23, m23, racc23);
        }
        float rlo, rhi, r2lo, r2hi;
        upk2(racc01, rlo, rhi);
        upk2(racc23, r2lo, r2hi);
        const float r = (rlo + rhi) + (r2lo + r2hi);

        acc = fmaf(vmask, r * (inv * inv), acc);
    }

    // block reduction (warp sum covers all 8 rows' lane partials)
    #pragma unroll
    for (int off = 16; off > 0; off >>= 1)
        acc += __shfl_xor_sync(FULL, acc, off);

    __shared__ float warpSums[BLOCK_T / 32];
    if (lane == 0) warpSums[wid] = acc;
    __syncthreads();

    __shared__ bool isLast;
    if (threadIdx.x == 0) {
        float sm = 0.0f;
        #pragma unroll
        for (int i = 0; i < BLOCK_T / 32; i++) sm += warpSums[i];
        g_partials[blockIdx.x] = sm;
        __threadfence();
        unsigned ticket = atomicAdd(&g_count, 1u);
        isLast = (ticket == (unsigned)(gridDim.x - 1));
    }
    __syncthreads();

    // last block reduces all partials (deterministic order) and resets counter
    if (isLast) {
        float sm = 0.0f;
        for (int i = threadIdx.x; i < GRID_B; i += BLOCK_T)
            sm += ((volatile float*)g_partials)[i];

        #pragma unroll
        for (int off = 16; off > 0; off >>= 1)
            sm += __shfl_xor_sync(FULL, sm, off);

        __shared__ float finalSums[BLOCK_T / 32];
        if (lane == 0) finalSums[wid] = sm;
        __syncthreads();

        if (threadIdx.x == 0) {
            float tot = 0.0f;
            #pragma unroll
            for (int i = 0; i < BLOCK_T / 32; i++) tot += finalSums[i];
            out[0] = tot / (float)B;
            g_count = 0;   // reset for next graph replay
        }
    }
}

extern "C" void kernel_launch(void* const* d_in, const int* in_sizes, int n_in,
                              void* d_out, int out_size)
{
    const float* y_hat = (const float*)d_in[0];
    const int*   t     = (const int*)d_in[1];
    const int*   e     = (const int*)d_in[2];
    float*       out   = (float*)d_out;
    const int B = in_sizes[1];   // element count of t

    survemd_main<<<GRID_B, BLOCK_T>>>(y_hat, t, e, out, B);
}

// round 16
// speedup vs baseline: 1.4217x; 1.0048x over previous
#include <cuda_runtime.h>
#include <cuda_bf16.h>

// SurvEMD fused forward (math: see prior rounds). Base = R15 (best, 53.6us).
// R15->R16: counted main loop with pointer increments (removes min-clamp,
// vmask FFMA, and per-iteration IMAD addressing from the hot loop; ~10
// slots/iter). Generic masked tail preserved. Everything else untouched:
// interleaved LDG.128, width-4 scan, tot-space f32x2 loss, launch_bounds(256,5).

#define NBINS       64
#define BLOCK_T     256
#define GRID_B      2048
#define EXP_NEG20   2.0611536e-09f   // expf(-20.0f)
#define FULL        0xFFFFFFFFu

__device__ float    g_partials[GRID_B];
__device__ unsigned g_count;         // zero-init; reset by last block each launch

__device__ __forceinline__ float frcp(float x) {
    float r;
    asm("rcp.approx.f32 %0, %1;" : "=f"(r) : "f"(x));
    return r;
}

__device__ __forceinline__ unsigned long long pk2(float lo, float hi) {
    unsigned long long r;
    asm("mov.b64 %0, {%1, %2};" : "=l"(r) : "f"(lo), "f"(hi));
    return r;
}
__device__ __forceinline__ unsigned long long fma2(unsigned long long a,
                                                   unsigned long long b,
                                                   unsigned long long c) {
    unsigned long long d;
    asm("fma.rn.f32x2 %0, %1, %2, %3;" : "=l"(d) : "l"(a), "l"(b), "l"(c));
    return d;
}
__device__ __forceinline__ unsigned long long add2(unsigned long long a,
                                                   unsigned long long b) {
    unsigned long long d;
    asm("add.rn.f32x2 %0, %1, %2;" : "=l"(d) : "l"(a), "l"(b));
    return d;
}
__device__ __forceinline__ void upk2(unsigned long long v, float& lo, float& hi) {
    asm("mov.b64 {%0, %1}, %2;" : "=f"(lo), "=f"(hi) : "l"(v));
}

// One row's loss given loaded y chunks (lane owns f4 chunks 4c+s).
__device__ __forceinline__ float row_body(int tr, int er, const float4* ya,
                                          float b0f, float b1f, float b2f, float b3f,
                                          unsigned long long b01, unsigned long long b23,
                                          int s)
{
    const bool  cen = (er == 0);
    const float tf  = (float)tr;
    const float kf  = cen ? (64.0f - tf) : 1.0f;
    const float q1  = frcp(fmaf(64.0f - kf, EXP_NEG20, kf));
    const float q0  = EXP_NEG20 * q1;
    const float dq  = q1 - q0;
    const float thr = cen ? tf : 3.0e38f;
    const float isc = cen ? 0.015625f : 1.0f;
    const float nb  = -tf * isc;
    const float ndqe = cen ? (dq * -64.0f) : -dq;

    // exps + in-lane inclusive partials per 4-element chunk
    float sl[4][4];
    #pragma unroll
    for (int c = 0; c < 4; c++) {
        const float thrc = thr - 16.0f * (float)c;
        float e0 = __expf((b0f > thrc) ? 10.0f : ya[c].x);
        float e1 = __expf((b1f > thrc) ? 10.0f : ya[c].y);
        float e2 = __expf((b2f > thrc) ? 10.0f : ya[c].z);
        float e3 = __expf((b3f > thrc) ? 10.0f : ya[c].w);
        sl[c][0] = e0;
        sl[c][1] = sl[c][0] + e1;
        sl[c][2] = sl[c][1] + e2;
        sl[c][3] = sl[c][2] + e3;
    }

    // exclusive quad prefixes (unnormalized): width-4 shfl scan + carry
    float E[4];
    float carry = 0.0f;
    #pragma unroll
    for (int c = 0; c < 4; c++) {
        float incl = sl[c][3];
        float v = __shfl_up_sync(FULL, incl, 1, 4);
        if (s >= 1) incl += v;
        v = __shfl_up_sync(FULL, incl, 2, 4);
        if (s >= 2) incl += v;
        const float W = __shfl_sync(FULL, incl, 3, 4);   // chunk total
        E[c] = carry + (incl - sl[c][3]);
        carry += W;
    }

    const float tot   = carry;          // row softmax denominator (unnorm)
    const float inv   = frcp(tot);      // off critical path
    const float nq0t  = -q0 * tot;
    const float ndqet = ndqe * tot;
    const unsigned long long nq0t2  = pk2(nq0t, nq0t);
    const unsigned long long ndqet2 = pk2(ndqet, ndqet);

    // loss in tot-space, f32x2 packed:
    // m = (E + s) - tot*T ; r = sum m^2 ; loss = r * inv^2
    unsigned long long racc01 = 0ull, racc23 = 0ull;
    #pragma unroll
    for (int c = 0; c < 4; c++) {
        const float hq = fmaf(16.0f * (float)c, nq0t, E[c]);
        const float hb = fmaf(16.0f * (float)c, isc, nb);

        const float c0 = __saturatef(fmaf(b0f, isc, hb));
        const float c1 = __saturatef(fmaf(b1f, isc, hb));
        const float c2 = __saturatef(fmaf(b2f, isc, hb));
        const float c3 = __saturatef(fmaf(b3f, isc, hb));

        const unsigned long long hq2 = pk2(hq, hq);
        const unsigned long long u01 = fma2(b01, nq0t2, hq2);
        const unsigned long long u23 = fma2(b23, nq0t2, hq2);
        const unsigned long long w01 = fma2(pk2(c0, c1), ndqet2, u01);
        const unsigned long long w23 = fma2(pk2(c2, c3), ndqet2, u23);
        const unsigned long long m01 = add2(pk2(sl[c][0], sl[c][1]), w01);
        const unsigned long long m23 = add2(pk2(sl[c][2], sl[c][3]), w23);
        racc01 = fma2(m01, m01, racc01);
        racc23 = fma2(m23, m23, racc23);
    }
    float rlo, rhi, r2lo, r2hi;
    upk2(racc01, rlo, rhi);
    upk2(racc23, r2lo, r2hi);
    const float r = (rlo + rhi) + (r2lo + r2hi);

    return r * (inv * inv);
}

__global__ __launch_bounds__(BLOCK_T, 5)
void survemd_main(const float* __restrict__ y_hat,
                  const int* __restrict__ t_in,
                  const int* __restrict__ e_in,
                  float* __restrict__ out,
                  int B)
{
    const int lane = threadIdx.x & 31;
    const int s    = lane & 3;    // sub-lane within row (owns f4 indices 4c+s)
    const int g    = lane >> 2;   // row within the warp's 8-row group
    const int wid  = threadIdx.x >> 5;

    const int warpsPerBlock = BLOCK_T / 32;
    const int gwarp   = blockIdx.x * warpsPerBlock + wid;
    const int wstride = GRID_B * warpsPerBlock * 8;     // rows per grid-stride step
    const int myrow   = gwarp * 8 + g;                  // < wstride always

    // per-lane element base: jp1(c,i) = (4s + i + 1) + 16c
    const float b0f = (float)(4 * s + 1);
    const float b1f = b0f + 1.0f;
    const float b2f = b0f + 2.0f;
    const float b3f = b0f + 3.0f;
    const unsigned long long b01 = pk2(b0f, b1f);
    const unsigned long long b23 = pk2(b2f, b3f);

    const int nIter   = B / wstride;        // 8 for the bench shape
    const int remBase = nIter * wstride;    // == B for the bench shape

    const int*    tp = t_in + myrow;
    const int*    ep = e_in + myrow;
    const float4* yp = (const float4*)y_hat + (size_t)myrow * 16 + s;

    float acc = 0.0f;

    #pragma unroll 1
    for (int k = 0; k < nIter; k++) {
        const int tr = *tp;
        const int er = *ep;
        float4 ya[4];
        ya[0] = yp[0];
        ya[1] = yp[4];
        ya[2] = yp[8];
        ya[3] = yp[12];

        acc += row_body(tr, er, ya, b0f, b1f, b2f, b3f, b01, b23, s);

        tp += wstride;
        ep += wstride;
        yp += (size_t)wstride * 16;
    }

    // generic masked tail (never taken when B % wstride == 0)
    if (remBase < B) {
        const int row  = remBase + myrow;
        const int rowc = min(row, B - 1);
        const float vm = (row < B) ? 1.0f : 0.0f;
        const int tr = t_in[rowc];
        const int er = e_in[rowc];
        const float4* zp = (const float4*)y_hat + (size_t)rowc * 16 + s;
        float4 ya[4] = {zp[0], zp[4], zp[8], zp[12]};
        acc = fmaf(vm, row_body(tr, er, ya, b0f, b1f, b2f, b3f, b01, b23, s), acc);
    }

    // block reduction (warp sum covers all 8 rows' lane partials)
    #pragma unroll
    for (int off = 16; off > 0; off >>= 1)
        acc += __shfl_xor_sync(FULL, acc, off);

    __shared__ float warpSums[BLOCK_T / 32];
    if (lane == 0) warpSums[wid] = acc;
    __syncthreads();

    __shared__ bool isLast;
    if (threadIdx.x == 0) {
        float sm = 0.0f;
        #pragma unroll
        for (int i = 0; i < BLOCK_T / 32; i++) sm += warpSums[i];
        g_partials[blockIdx.x] = sm;
        __threadfence();
        unsigned ticket = atomicAdd(&g_count, 1u);
        isLast = (ticket == (unsigned)(gridDim.x - 1));
    }
    __syncthreads();

    // last block reduces all partials (deterministic order) and resets counter
    if (isLast) {
        float sm = 0.0f;
        for (int i = threadIdx.x; i < GRID_B; i += BLOCK_T)
            sm += ((volatile float*)g_partials)[i];

        #pragma unroll
        for (int off = 16; off > 0; off >>= 1)
            sm += __shfl_xor_sync(FULL, sm, off);

        __shared__ float finalSums[BLOCK_T / 32];
        if (lane == 0) finalSums[wid] = sm;
        __syncthreads();

        if (threadIdx.x == 0) {
            float tot = 0.0f;
            #pragma unroll
            for (int i = 0; i < BLOCK_T / 32; i++) tot += finalSums[i];
            out[0] = tot / (float)B;
            g_count = 0;   // reset for next graph replay
        }
    }
}

extern "C" void kernel_launch(void* const* d_in, const int* in_sizes, int n_in,
                              void* d_out, int out_size)
{
    const float* y_hat = (const float*)d_in[0];
    const int*   t     = (const int*)d_in[1];
    const int*   e     = (const int*)d_in[2];
    float*       out   = (float*)d_out;
    const int B = in_sizes[1];   // element count of t

    survemd_main<<<GRID_B, BLOCK_T>>>(y_hat, t, e, out, B);
}